// round 5
// baseline (speedup 1.0000x reference)
#include <cuda_runtime.h>
#include <cstdint>
#include <cstddef>

#define NMAX 100000
#define EMAX 1600000
#define HDIM 128

// ---------------- scratch (static device arrays; no allocation) ----------------
__device__ float g_h   [(size_t)NMAX * HDIM];
__device__ float g_xp  [(size_t)NMAX * HDIM];
__device__ float g_m   [(size_t)NMAX * HDIM];
__device__ float g_xp0 [(size_t)NMAX * 2];
__device__ float g_inv [NMAX];
__device__ int   g_icnt[NMAX];
__device__ int   g_rowptr[NMAX + 1];
__device__ int   g_woff[NMAX];
__device__ int   g_csrc[EMAX];

static inline int cdiv(int a, int b) { return (a + b - 1) / b; }

__device__ __forceinline__ float4 ld4(const float* p) { return __ldg((const float4*)p); }

__device__ __forceinline__ uint32_t f2tf(float f) {
    uint32_t r; asm("cvt.rna.tf32.f32 %0, %1;" : "=r"(r) : "f"(f)); return r;
}
__device__ __forceinline__ void tfsplit(float v, uint32_t& hi, uint32_t& lo) {
    hi = f2tf(v);
    lo = f2tf(v - __uint_as_float(hi));
}
__device__ __forceinline__ void mma_tf32(float* c, const uint32_t* a, const uint32_t* b) {
    asm volatile(
        "mma.sync.aligned.m16n8k8.row.col.f32.tf32.tf32.f32 "
        "{%0,%1,%2,%3}, {%4,%5,%6,%7}, {%8,%9}, {%0,%1,%2,%3};"
        : "+f"(c[0]), "+f"(c[1]), "+f"(c[2]), "+f"(c[3])
        : "r"(a[0]), "r"(a[1]), "r"(a[2]), "r"(a[3]), "r"(b[0]), "r"(b[1]));
}

// ---------------- CSR build ----------------
__global__ void count_k(const int* __restrict__ dst, int* __restrict__ cnt, int E) {
    int e = blockIdx.x * blockDim.x + threadIdx.x;
    if (e < E) atomicAdd(&cnt[__ldg(dst + e)], 1);
}

__global__ void scan_k(const int* __restrict__ cnt, int* __restrict__ rowptr,
                       int* __restrict__ woff, float* __restrict__ inv, int Nn) {
    __shared__ int ssum[1024];
    int t = threadIdx.x;
    int CH = (Nn + 1023) / 1024;
    int beg = t * CH, end = min(beg + CH, Nn);
    int s = 0;
    for (int i = beg; i < end; i++) s += __ldg(cnt + i);
    ssum[t] = s;
    __syncthreads();
    for (int o = 1; o < 1024; o <<= 1) {
        int v = (t >= o) ? ssum[t - o] : 0;
        __syncthreads();
        ssum[t] += v;
        __syncthreads();
    }
    int run = (t > 0) ? ssum[t - 1] : 0;
    for (int i = beg; i < end; i++) {
        int c = __ldg(cnt + i);
        rowptr[i] = run;
        woff[i] = run;
        inv[i] = 1.0f / fmaxf((float)c, 1.0f);
        run += c;
    }
    if (t == 1023) rowptr[Nn] = ssum[1023];
}

__global__ void scatter_k(const int* __restrict__ src, const int* __restrict__ dst,
                          int* __restrict__ woff, int* __restrict__ csrc, int E) {
    int e = blockIdx.x * blockDim.x + threadIdx.x;
    if (e >= E) return;
    int d = __ldg(dst + e);
    int pos = atomicAdd(&woff[d], 1);
    csrc[pos] = __ldg(src + e);
}

// ---------------- layer 0 (IN = 2) ----------------
__global__ void l0xp_k(const float* __restrict__ x, const float* __restrict__ Wp,
                       const float* __restrict__ bp, float* __restrict__ xp0, int Nn) {
    int n = blockIdx.x * blockDim.x + threadIdx.x;
    if (n >= Nn) return;
    float x0 = x[2 * n], x1 = x[2 * n + 1];
    float w00 = __ldg(Wp + 0), w01 = __ldg(Wp + 1), w10 = __ldg(Wp + 2), w11 = __ldg(Wp + 3);
    xp0[2 * n]     = fmaxf(x0 * w00 + x1 * w10 + __ldg(bp + 0), 0.0f);
    xp0[2 * n + 1] = fmaxf(x0 * w01 + x1 * w11 + __ldg(bp + 1), 0.0f);
}

// CSR aggregation (2-dim) + combine0 + LayerNorm fused: warp per node
__global__ void combine0_ln_k(const int* __restrict__ rowptr, const int* __restrict__ csrc,
                              const float* __restrict__ inv,
                              const float* __restrict__ xp0, const float* __restrict__ Wl,
                              const float* __restrict__ bl, const float* __restrict__ Wr,
                              const float* __restrict__ lnw, const float* __restrict__ lnb,
                              float* __restrict__ h, int Nn) {
    int gw = (blockIdx.x * blockDim.x + threadIdx.x) >> 5;
    int lane = threadIdx.x & 31;
    if (gw >= Nn) return;
    int beg = __ldg(rowptr + gw), end = __ldg(rowptr + gw + 1);
    float a0 = 0.0f, a1 = 0.0f;
    for (int e = beg + lane; e < end; e += 32) {
        int s2 = __ldg(csrc + e);
        a0 += __ldg(xp0 + 2 * s2);
        a1 += __ldg(xp0 + 2 * s2 + 1);
    }
#pragma unroll
    for (int o = 16; o; o >>= 1) {
        a0 += __shfl_xor_sync(0xffffffffu, a0, o);
        a1 += __shfl_xor_sync(0xffffffffu, a1, o);
    }
    float iv = __ldg(inv + gw);
    float m0 = a0 * iv, m1 = a1 * iv;
    float x0 = __ldg(xp0 + 2 * gw), x1 = __ldg(xp0 + 2 * gw + 1);
    float v[4];
    float s = 0.0f;
#pragma unroll
    for (int j = 0; j < 4; j++) {
        int c = lane + 32 * j;
        v[j] = m0 * __ldg(Wl + c) + m1 * __ldg(Wl + 128 + c) + __ldg(bl + c)
             + x0 * __ldg(Wr + c) + x1 * __ldg(Wr + 128 + c);
        s += v[j];
    }
#pragma unroll
    for (int o = 16; o; o >>= 1) s += __shfl_xor_sync(0xffffffffu, s, o);
    float mu = s * (1.0f / 128.0f);
    float vs = 0.0f;
#pragma unroll
    for (int j = 0; j < 4; j++) { float d = v[j] - mu; vs += d * d; }
#pragma unroll
    for (int o = 16; o; o >>= 1) vs += __shfl_xor_sync(0xffffffffu, vs, o);
    float rs = rsqrtf(vs * (1.0f / 128.0f) + 1e-5f);
#pragma unroll
    for (int j = 0; j < 4; j++) {
        int c = lane + 32 * j;
        h[(size_t)gw * 128 + c] = (v[j] - mu) * rs * __ldg(lnw + c) + __ldg(lnb + c);
    }
}

// ---------------- CSR aggregation, H = 128: warp per node, no atomics ----------------
__global__ void agg_csr_k(const float* __restrict__ xp, const int* __restrict__ rowptr,
                          const int* __restrict__ csrc, const float* __restrict__ inv,
                          float* __restrict__ m, int Nn) {
    int n = (blockIdx.x * blockDim.x + threadIdx.x) >> 5;
    int lane = threadIdx.x & 31;
    if (n >= Nn) return;
    int beg = __ldg(rowptr + n), end = __ldg(rowptr + n + 1);
    float4 acc = make_float4(0.f, 0.f, 0.f, 0.f);
    int e = beg;
    for (; e + 1 < end; e += 2) {
        int s0 = __ldg(csrc + e), s1 = __ldg(csrc + e + 1);
        float4 v0 = __ldg((const float4*)(xp + (size_t)s0 * 128) + lane);
        float4 v1 = __ldg((const float4*)(xp + (size_t)s1 * 128) + lane);
        acc.x += v0.x + v1.x; acc.y += v0.y + v1.y;
        acc.z += v0.z + v1.z; acc.w += v0.w + v1.w;
    }
    if (e < end) {
        int s0 = __ldg(csrc + e);
        float4 v0 = __ldg((const float4*)(xp + (size_t)s0 * 128) + lane);
        acc.x += v0.x; acc.y += v0.y; acc.z += v0.z; acc.w += v0.w;
    }
    float iv = __ldg(inv + n);
    acc.x *= iv; acc.y *= iv; acc.z *= iv; acc.w *= iv;
    *(float4*)(m + (size_t)n * 128 + lane * 4) = acc;
}

// ---------------- 3xTF32 tensor-core GEMM, register-prefetch pipelined ----------------
// BM=128, BN=128, BK=16, 256 threads, warps 2(m) x 4(n), warp tile 64x32.
// MODE 0: C = relu(A[M,128] @ B[128,128] + bias)
// MODE 1: C = [m | xp][M,256] @ [Wl;Wr] + bias
// MODE 2: out[row] = relu([h[g1]|h[g2]] @ e_W1 + e_b1) . W2 + b2
#define AST 20
#define BST 136
template <int MODE>
__global__ __launch_bounds__(256, 2) void mma_gemm_k(
    const float* __restrict__ A, const float* __restrict__ A2,
    const int* __restrict__ g1, const int* __restrict__ g2,
    const float* __restrict__ B, const float* __restrict__ B2,
    const float* __restrict__ bias, const float* __restrict__ W2, const float* __restrict__ b2,
    float* __restrict__ C, int M) {
    constexpr int KDIM = (MODE == 0) ? 128 : 256;
    __shared__ uint32_t AsH[128 * AST];
    __shared__ uint32_t AsL[128 * AST];
    __shared__ uint32_t BsH[16 * BST];
    __shared__ uint32_t BsL[16 * BST];
    __shared__ float red[128];

    const int tid = threadIdx.x;
    const int brow = blockIdx.x * 128;
    const int lane = tid & 31;
    const int wid = tid >> 5;
    const int wm = wid & 1;
    const int wn = wid >> 1;
    const int grp = lane >> 2;
    const int qid = lane & 3;

    // A-load geometry (per thread, two float4 loads p=0,1)
    const int am = tid >> 2;              // 0..63 (p adds 64)
    const int akc = (tid & 3) * 4;        // 0,4,8,12
    // B-load geometry
    const int bk = tid >> 5;              // 0..7 (p adds 8)
    const int bnc = (tid & 31) * 4;

    if (MODE == 2 && tid < 128) red[tid] = 0.0f;

    float acc[4][4][4];
#pragma unroll
    for (int mt = 0; mt < 4; mt++)
#pragma unroll
        for (int nt = 0; nt < 4; nt++)
#pragma unroll
            for (int r = 0; r < 4; r++) acc[mt][nt][r] = 0.0f;

    auto loadA = [&](int k0, int p) -> float4 {
        int m = am + p * 64;
        int grow = brow + m;
        int k = k0 + akc;
        float4 v = make_float4(0.f, 0.f, 0.f, 0.f);
        if (grow < M) {
            if (MODE == 0) {
                v = ld4(A + (size_t)grow * 128 + k);
            } else if (MODE == 1) {
                v = (k < 128) ? ld4(A + (size_t)grow * 128 + k)
                              : ld4(A2 + (size_t)grow * 128 + (k - 128));
            } else {
                int node = (k < 128) ? __ldg(g1 + grow) : __ldg(g2 + grow);
                int kk = (k < 128) ? k : (k - 128);
                v = ld4(A + (size_t)node * 128 + kk);
            }
        }
        return v;
    };
    auto loadB = [&](int k0, int p) -> float4 {
        int gk = k0 + bk + p * 8;
        if (MODE == 1)
            return (gk < 128) ? ld4(B + (size_t)gk * 128 + bnc)
                              : ld4(B2 + (size_t)(gk - 128) * 128 + bnc);
        return ld4(B + (size_t)gk * 128 + bnc);
    };

    // prologue: prefetch first tile into registers
    float4 va0 = loadA(0, 0), va1 = loadA(0, 1);
    float4 vb0 = loadB(0, 0), vb1 = loadB(0, 1);

#pragma unroll 1
    for (int k0 = 0; k0 < KDIM; k0 += 16) {
        // ---- split + store current tile to smem ----
        {
            uint4 th, tl;
            tfsplit(va0.x, th.x, tl.x); tfsplit(va0.y, th.y, tl.y);
            tfsplit(va0.z, th.z, tl.z); tfsplit(va0.w, th.w, tl.w);
            *(uint4*)&AsH[am * AST + akc] = th;
            *(uint4*)&AsL[am * AST + akc] = tl;
            tfsplit(va1.x, th.x, tl.x); tfsplit(va1.y, th.y, tl.y);
            tfsplit(va1.z, th.z, tl.z); tfsplit(va1.w, th.w, tl.w);
            *(uint4*)&AsH[(am + 64) * AST + akc] = th;
            *(uint4*)&AsL[(am + 64) * AST + akc] = tl;
            tfsplit(vb0.x, th.x, tl.x); tfsplit(vb0.y, th.y, tl.y);
            tfsplit(vb0.z, th.z, tl.z); tfsplit(vb0.w, th.w, tl.w);
            *(uint4*)&BsH[bk * BST + bnc] = th;
            *(uint4*)&BsL[bk * BST + bnc] = tl;
            tfsplit(vb1.x, th.x, tl.x); tfsplit(vb1.y, th.y, tl.y);
            tfsplit(vb1.z, th.z, tl.z); tfsplit(vb1.w, th.w, tl.w);
            *(uint4*)&BsH[(bk + 8) * BST + bnc] = th;
            *(uint4*)&BsL[(bk + 8) * BST + bnc] = tl;
        }
        __syncthreads();

        // ---- issue prefetch LDGs for NEXT tile (overlap with compute) ----
        if (k0 + 16 < KDIM) {
            va0 = loadA(k0 + 16, 0); va1 = loadA(k0 + 16, 1);
            vb0 = loadB(k0 + 16, 0); vb1 = loadB(k0 + 16, 1);
        }

        // ---- compute from smem ----
#pragma unroll
        for (int kk = 0; kk < 16; kk += 8) {
            uint32_t ah[4][4], al[4][4];
#pragma unroll
            for (int mt = 0; mt < 4; mt++) {
                int r = wm * 64 + mt * 16 + grp;
                int o0 = r * AST + kk + qid;
                int o1 = (r + 8) * AST + kk + qid;
                ah[mt][0] = AsH[o0];     ah[mt][1] = AsH[o1];
                ah[mt][2] = AsH[o0 + 4]; ah[mt][3] = AsH[o1 + 4];
                al[mt][0] = AsL[o0];     al[mt][1] = AsL[o1];
                al[mt][2] = AsL[o0 + 4]; al[mt][3] = AsL[o1 + 4];
            }
#pragma unroll
            for (int nt = 0; nt < 4; nt++) {
                int c = wn * 32 + nt * 8 + grp;
                uint32_t bh[2], bl_[2];
                bh[0]  = BsH[(kk + qid) * BST + c];
                bh[1]  = BsH[(kk + qid + 4) * BST + c];
                bl_[0] = BsL[(kk + qid) * BST + c];
                bl_[1] = BsL[(kk + qid + 4) * BST + c];
#pragma unroll
                for (int mt = 0; mt < 4; mt++) {
                    mma_tf32(acc[mt][nt], ah[mt], bh);
                    mma_tf32(acc[mt][nt], al[mt], bh);
                    mma_tf32(acc[mt][nt], ah[mt], bl_);
                }
            }
        }
        __syncthreads();
    }

    float bv[4][2];
#pragma unroll
    for (int nt = 0; nt < 4; nt++) {
        int c = wn * 32 + nt * 8 + 2 * qid;
        bv[nt][0] = __ldg(bias + c);
        bv[nt][1] = __ldg(bias + c + 1);
    }

    if (MODE != 2) {
#pragma unroll
        for (int mt = 0; mt < 4; mt++) {
#pragma unroll
            for (int half = 0; half < 2; half++) {
                int row = brow + wm * 64 + mt * 16 + grp + half * 8;
                if (row < M) {
#pragma unroll
                    for (int nt = 0; nt < 4; nt++) {
                        int col = wn * 32 + nt * 8 + 2 * qid;
                        float2 o;
                        o.x = acc[mt][nt][half * 2 + 0] + bv[nt][0];
                        o.y = acc[mt][nt][half * 2 + 1] + bv[nt][1];
                        if (MODE == 0) { o.x = fmaxf(o.x, 0.f); o.y = fmaxf(o.y, 0.f); }
                        *(float2*)(C + (size_t)row * 128 + col) = o;
                    }
                }
            }
        }
    } else {
        float w2v[4][2];
#pragma unroll
        for (int nt = 0; nt < 4; nt++) {
            int c = wn * 32 + nt * 8 + 2 * qid;
            w2v[nt][0] = __ldg(W2 + c);
            w2v[nt][1] = __ldg(W2 + c + 1);
        }
#pragma unroll
        for (int mt = 0; mt < 4; mt++) {
#pragma unroll
            for (int half = 0; half < 2; half++) {
                float part = 0.0f;
#pragma unroll
                for (int nt = 0; nt < 4; nt++) {
                    part += fmaxf(acc[mt][nt][half * 2 + 0] + bv[nt][0], 0.f) * w2v[nt][0];
                    part += fmaxf(acc[mt][nt][half * 2 + 1] + bv[nt][1], 0.f) * w2v[nt][1];
                }
                part += __shfl_down_sync(0xffffffffu, part, 2);
                part += __shfl_down_sync(0xffffffffu, part, 1);
                if (qid == 0) {
                    int rloc = wm * 64 + mt * 16 + grp + half * 8;
                    atomicAdd(&red[rloc], part);
                }
            }
        }
        __syncthreads();
        if (tid < 128) {
            int row = brow + tid;
            if (row < M) C[row] = red[tid] + __ldg(b2);
        }
    }
}

// ---------------- LayerNorm in-place: warp per node ----------------
__global__ void ln_k(float* __restrict__ h, const float* __restrict__ lnw,
                     const float* __restrict__ lnb, int Nn) {
    int gw = (blockIdx.x * blockDim.x + threadIdx.x) >> 5;
    int lane = threadIdx.x & 31;
    if (gw >= Nn) return;
    float4 v = *(float4*)(h + (size_t)gw * 128 + lane * 4);
    float s = v.x + v.y + v.z + v.w;
#pragma unroll
    for (int o = 16; o; o >>= 1) s += __shfl_xor_sync(0xffffffffu, s, o);
    float mu = s * (1.0f / 128.0f);
    float dx = v.x - mu, dy = v.y - mu, dz = v.z - mu, dw = v.w - mu;
    float vs = dx * dx + dy * dy + dz * dz + dw * dw;
#pragma unroll
    for (int o = 16; o; o >>= 1) vs += __shfl_xor_sync(0xffffffffu, vs, o);
    float rs = rsqrtf(vs * (1.0f / 128.0f) + 1e-5f);
    float4 w = ld4(lnw + lane * 4), b = ld4(lnb + lane * 4);
    v.x = dx * rs * w.x + b.x;
    v.y = dy * rs * w.y + b.y;
    v.z = dz * rs * w.z + b.z;
    v.w = dw * rs * w.w + b.w;
    *(float4*)(h + (size_t)gw * 128 + lane * 4) = v;
}

// ---------------- launch ----------------
extern "C" void kernel_launch(void* const* d_in, const int* in_sizes, int n_in,
                              void* d_out, int out_size) {
    const float* x     = (const float*)d_in[0];
    const int*   ei    = (const int*)d_in[1];
    const int*   eli   = (const int*)d_in[2];
    const float* p0_Wp = (const float*)d_in[3];
    const float* p0_bp = (const float*)d_in[4];
    const float* p0_Wl = (const float*)d_in[5];
    const float* p0_bl = (const float*)d_in[6];
    const float* p0_Wr = (const float*)d_in[7];
    const float* Wp_s  = (const float*)d_in[8];
    const float* bp_s  = (const float*)d_in[9];
    const float* Wl_s  = (const float*)d_in[10];
    const float* bl_s  = (const float*)d_in[11];
    const float* Wr_s  = (const float*)d_in[12];
    const float* ln_w  = (const float*)d_in[13];
    const float* ln_b  = (const float*)d_in[14];
    const float* e_W1  = (const float*)d_in[15];
    const float* e_b1  = (const float*)d_in[16];
    const float* e_W2  = (const float*)d_in[17];
    const float* e_b2  = (const float*)d_in[18];
    float* out = (float*)d_out;

    const int Nn = in_sizes[0] / 2;
    const int E  = in_sizes[1] / 2;
    const int Q  = in_sizes[2] / 2;

    float *p_h, *p_xp, *p_m, *p_xp0, *p_inv;
    int *p_icnt, *p_rowptr, *p_woff, *p_csrc;
    cudaGetSymbolAddress((void**)&p_h,      g_h);
    cudaGetSymbolAddress((void**)&p_xp,     g_xp);
    cudaGetSymbolAddress((void**)&p_m,      g_m);
    cudaGetSymbolAddress((void**)&p_xp0,    g_xp0);
    cudaGetSymbolAddress((void**)&p_inv,    g_inv);
    cudaGetSymbolAddress((void**)&p_icnt,   g_icnt);
    cudaGetSymbolAddress((void**)&p_rowptr, g_rowptr);
    cudaGetSymbolAddress((void**)&p_woff,   g_woff);
    cudaGetSymbolAddress((void**)&p_csrc,   g_csrc);

    const int* src = ei;
    const int* dst = ei + E;

    // ---- CSR build (reused by all 3 layers) ----
    cudaMemsetAsync(p_icnt, 0, (size_t)Nn * sizeof(int));
    count_k<<<cdiv(E, 256), 256>>>(dst, p_icnt, E);
    scan_k<<<1, 1024>>>(p_icnt, p_rowptr, p_woff, p_inv, Nn);
    scatter_k<<<cdiv(E, 256), 256>>>(src, dst, p_woff, p_csrc, E);

    // ---- layer 0 (IN=2) ----
    l0xp_k<<<cdiv(Nn, 256), 256>>>(x, p0_Wp, p0_bp, p_xp0, Nn);
    combine0_ln_k<<<cdiv(Nn, 8), 256>>>(p_rowptr, p_csrc, p_inv, p_xp0,
                                        p0_Wl, p0_bl, p0_Wr, ln_w, ln_b, p_h, Nn);

    // ---- layers 1..2 (H -> H) ----
    for (int i = 0; i < 2; i++) {
        mma_gemm_k<0><<<cdiv(Nn, 128), 256>>>(p_h, nullptr, nullptr, nullptr,
                                              Wp_s + (size_t)i * HDIM * HDIM, nullptr,
                                              bp_s + (size_t)i * HDIM, nullptr, nullptr,
                                              p_xp, Nn);
        agg_csr_k<<<cdiv(Nn, 8), 256>>>(p_xp, p_rowptr, p_csrc, p_inv, p_m, Nn);
        mma_gemm_k<1><<<cdiv(Nn, 128), 256>>>(p_m, p_xp, nullptr, nullptr,
                                              Wl_s + (size_t)i * HDIM * HDIM,
                                              Wr_s + (size_t)i * HDIM * HDIM,
                                              bl_s + (size_t)i * HDIM, nullptr, nullptr,
                                              p_h, Nn);
        ln_k<<<cdiv(Nn, 8), 256>>>(p_h, ln_w + (size_t)(i + 1) * HDIM,
                                   ln_b + (size_t)(i + 1) * HDIM, Nn);
    }

    // ---- edge MLP (fused logits) ----
    mma_gemm_k<2><<<cdiv(Q, 128), 256>>>(p_h, nullptr, eli, eli + Q,
                                         e_W1, nullptr, e_b1, e_W2, e_b2, out, Q);
}

// round 6
// speedup vs baseline: 1.0506x; 1.0506x over previous
#include <cuda_runtime.h>
#include <cstdint>
#include <cstddef>

#define NMAX 100000
#define EMAX 1600000
#define HDIM 128

// ---------------- scratch (static device arrays; no allocation) ----------------
__device__ float g_h   [(size_t)NMAX * HDIM];
__device__ float g_xp  [(size_t)NMAX * HDIM];
__device__ float g_m   [(size_t)NMAX * HDIM];
__device__ float g_xp0 [(size_t)NMAX * 2];
__device__ float g_inv [NMAX];
__device__ int   g_icnt[NMAX];
__device__ int   g_rowptr[NMAX + 1];
__device__ int   g_woff[NMAX];
__device__ int   g_csrc[EMAX];

static inline int cdiv(int a, int b) { return (a + b - 1) / b; }

__device__ __forceinline__ float4 ld4(const float* p) { return __ldg((const float4*)p); }

__device__ __forceinline__ uint32_t f2tf(float f) {
    uint32_t r; asm("cvt.rna.tf32.f32 %0, %1;" : "=r"(r) : "f"(f)); return r;
}
__device__ __forceinline__ void tfsplit(float v, uint32_t& hi, uint32_t& lo) {
    hi = f2tf(v);
    lo = f2tf(v - __uint_as_float(hi));
}
__device__ __forceinline__ void mma_tf32(float* c, const uint32_t* a, const uint32_t* b) {
    asm volatile(
        "mma.sync.aligned.m16n8k8.row.col.f32.tf32.tf32.f32 "
        "{%0,%1,%2,%3}, {%4,%5,%6,%7}, {%8,%9}, {%0,%1,%2,%3};"
        : "+f"(c[0]), "+f"(c[1]), "+f"(c[2]), "+f"(c[3])
        : "r"(a[0]), "r"(a[1]), "r"(a[2]), "r"(a[3]), "r"(b[0]), "r"(b[1]));
}

// ---------------- CSR build ----------------
__global__ void count_k(const int* __restrict__ dst, int* __restrict__ cnt, int E) {
    int e = blockIdx.x * blockDim.x + threadIdx.x;
    if (e < E) atomicAdd(&cnt[__ldg(dst + e)], 1);
}

__global__ void scan_k(const int* __restrict__ cnt, int* __restrict__ rowptr,
                       int* __restrict__ woff, float* __restrict__ inv, int Nn) {
    __shared__ int ssum[1024];
    int t = threadIdx.x;
    int CH = (Nn + 1023) / 1024;
    int beg = t * CH, end = min(beg + CH, Nn);
    int s = 0;
    for (int i = beg; i < end; i++) s += __ldg(cnt + i);
    ssum[t] = s;
    __syncthreads();
    for (int o = 1; o < 1024; o <<= 1) {
        int v = (t >= o) ? ssum[t - o] : 0;
        __syncthreads();
        ssum[t] += v;
        __syncthreads();
    }
    int run = (t > 0) ? ssum[t - 1] : 0;
    for (int i = beg; i < end; i++) {
        int c = __ldg(cnt + i);
        rowptr[i] = run;
        woff[i] = run;
        inv[i] = 1.0f / fmaxf((float)c, 1.0f);
        run += c;
    }
    if (t == 1023) rowptr[Nn] = ssum[1023];
}

__global__ void scatter_k(const int* __restrict__ src, const int* __restrict__ dst,
                          int* __restrict__ woff, int* __restrict__ csrc, int E) {
    int e = blockIdx.x * blockDim.x + threadIdx.x;
    if (e >= E) return;
    int d = __ldg(dst + e);
    int pos = atomicAdd(&woff[d], 1);
    csrc[pos] = __ldg(src + e);
}

// ---------------- layer 0 (IN = 2); also zeroes icnt for CSR build ----------------
__global__ void l0xp_k(const float* __restrict__ x, const float* __restrict__ Wp,
                       const float* __restrict__ bp, float* __restrict__ xp0,
                       int* __restrict__ icnt, int Nn) {
    int n = blockIdx.x * blockDim.x + threadIdx.x;
    if (n >= Nn) return;
    icnt[n] = 0;
    float x0 = x[2 * n], x1 = x[2 * n + 1];
    float w00 = __ldg(Wp + 0), w01 = __ldg(Wp + 1), w10 = __ldg(Wp + 2), w11 = __ldg(Wp + 3);
    xp0[2 * n]     = fmaxf(x0 * w00 + x1 * w10 + __ldg(bp + 0), 0.0f);
    xp0[2 * n + 1] = fmaxf(x0 * w01 + x1 * w11 + __ldg(bp + 1), 0.0f);
}

// CSR aggregation (2-dim) + combine0 + LayerNorm fused: warp per node
__global__ void combine0_ln_k(const int* __restrict__ rowptr, const int* __restrict__ csrc,
                              const float* __restrict__ inv,
                              const float* __restrict__ xp0, const float* __restrict__ Wl,
                              const float* __restrict__ bl, const float* __restrict__ Wr,
                              const float* __restrict__ lnw, const float* __restrict__ lnb,
                              float* __restrict__ h, int Nn) {
    int gw = (blockIdx.x * blockDim.x + threadIdx.x) >> 5;
    int lane = threadIdx.x & 31;
    if (gw >= Nn) return;
    int beg = __ldg(rowptr + gw), end = __ldg(rowptr + gw + 1);
    float a0 = 0.0f, a1 = 0.0f;
    for (int e = beg + lane; e < end; e += 32) {
        int s2 = __ldg(csrc + e);
        a0 += __ldg(xp0 + 2 * s2);
        a1 += __ldg(xp0 + 2 * s2 + 1);
    }
#pragma unroll
    for (int o = 16; o; o >>= 1) {
        a0 += __shfl_xor_sync(0xffffffffu, a0, o);
        a1 += __shfl_xor_sync(0xffffffffu, a1, o);
    }
    float iv = __ldg(inv + gw);
    float m0 = a0 * iv, m1 = a1 * iv;
    float x0 = __ldg(xp0 + 2 * gw), x1 = __ldg(xp0 + 2 * gw + 1);
    float v[4];
    float s = 0.0f;
#pragma unroll
    for (int j = 0; j < 4; j++) {
        int c = lane + 32 * j;
        v[j] = m0 * __ldg(Wl + c) + m1 * __ldg(Wl + 128 + c) + __ldg(bl + c)
             + x0 * __ldg(Wr + c) + x1 * __ldg(Wr + 128 + c);
        s += v[j];
    }
#pragma unroll
    for (int o = 16; o; o >>= 1) s += __shfl_xor_sync(0xffffffffu, s, o);
    float mu = s * (1.0f / 128.0f);
    float vs = 0.0f;
#pragma unroll
    for (int j = 0; j < 4; j++) { float d = v[j] - mu; vs += d * d; }
#pragma unroll
    for (int o = 16; o; o >>= 1) vs += __shfl_xor_sync(0xffffffffu, vs, o);
    float rs = rsqrtf(vs * (1.0f / 128.0f) + 1e-5f);
#pragma unroll
    for (int j = 0; j < 4; j++) {
        int c = lane + 32 * j;
        h[(size_t)gw * 128 + c] = (v[j] - mu) * rs * __ldg(lnw + c) + __ldg(lnb + c);
    }
}

// ---------------- CSR aggregation, H = 128: warp per node, no atomics ----------------
__global__ void agg_csr_k(const float* __restrict__ xp, const int* __restrict__ rowptr,
                          const int* __restrict__ csrc, const float* __restrict__ inv,
                          float* __restrict__ m, int Nn) {
    int n = (blockIdx.x * blockDim.x + threadIdx.x) >> 5;
    int lane = threadIdx.x & 31;
    if (n >= Nn) return;
    int beg = __ldg(rowptr + n), end = __ldg(rowptr + n + 1);
    float4 acc = make_float4(0.f, 0.f, 0.f, 0.f);
    int e = beg;
    for (; e + 1 < end; e += 2) {
        int s0 = __ldg(csrc + e), s1 = __ldg(csrc + e + 1);
        float4 v0 = __ldg((const float4*)(xp + (size_t)s0 * 128) + lane);
        float4 v1 = __ldg((const float4*)(xp + (size_t)s1 * 128) + lane);
        acc.x += v0.x + v1.x; acc.y += v0.y + v1.y;
        acc.z += v0.z + v1.z; acc.w += v0.w + v1.w;
    }
    if (e < end) {
        int s0 = __ldg(csrc + e);
        float4 v0 = __ldg((const float4*)(xp + (size_t)s0 * 128) + lane);
        acc.x += v0.x; acc.y += v0.y; acc.z += v0.z; acc.w += v0.w;
    }
    float iv = __ldg(inv + n);
    acc.x *= iv; acc.y *= iv; acc.z *= iv; acc.w *= iv;
    *(float4*)(m + (size_t)n * 128 + lane * 4) = acc;
}

// ---------------- 3xTF32 tensor-core GEMM, BK=8 double-buffered smem ----------------
// BM=128, BN=128, BK=8, 256 threads, warps 2(m) x 4(n), warp tile 64x32.
// MODE 0: C = relu(A[M,128] @ B[128,128] + bias)
// MODE 1: C = LN([m | xp][M,256] @ [Wl;Wr] + bias) * lnw + lnb   (LN fused)
// MODE 2: out[row] = relu([h[g1]|h[g2]] @ e_W1 + e_b1) . W2 + b2
#define AST 12          // As k-stride (u32), 8 + 4 pad
#define BST 136         // Bs n-stride (u32)
#define A_SZ (128 * AST)       // 1536
#define B_SZ (8 * BST)         // 1088
#define STG_SZ (2 * A_SZ + 2 * B_SZ)   // 5248 u32 per stage
template <int MODE>
__global__ __launch_bounds__(256, 2) void mma_gemm_k(
    const float* __restrict__ A, const float* __restrict__ A2,
    const int* __restrict__ g1, const int* __restrict__ g2,
    const float* __restrict__ B, const float* __restrict__ B2,
    const float* __restrict__ bias, const float* __restrict__ W2, const float* __restrict__ b2,
    const float* __restrict__ lnw, const float* __restrict__ lnb,
    float* __restrict__ C, int M) {
    constexpr int KDIM = (MODE == 0) ? 128 : 256;
    constexpr int NT = KDIM / 8;
    __shared__ uint32_t S[2 * STG_SZ];          // 42 KB
    __shared__ float s_r1[4 * 128];             // LN partial sums
    __shared__ float s_r2[4 * 128];
    __shared__ float s_mu[128];
    __shared__ float s_rs[128];
    __shared__ float red[128];

    const int tid = threadIdx.x;
    const int brow = blockIdx.x * 128;
    const int lane = tid & 31;
    const int wid = tid >> 5;
    const int wm = wid & 1;
    const int wn = wid >> 1;
    const int grp = lane >> 2;
    const int qid = lane & 3;

    // A-load geometry: one float4 per thread per stage: m = tid>>1, kc = (tid&1)*4
    const int am = tid >> 1;
    const int akc = (tid & 1) * 4;
    // B-load geometry: gk = tid>>5, nc = (tid&31)*4
    const int bk = tid >> 5;
    const int bnc = (tid & 31) * 4;

    if (MODE == 2 && tid < 128) red[tid] = 0.0f;

    float acc[4][4][4];
#pragma unroll
    for (int mt = 0; mt < 4; mt++)
#pragma unroll
        for (int nt = 0; nt < 4; nt++)
#pragma unroll
            for (int r = 0; r < 4; r++) acc[mt][nt][r] = 0.0f;

    auto loadA = [&](int k0) -> float4 {
        int grow = brow + am;
        int k = k0 + akc;
        float4 v = make_float4(0.f, 0.f, 0.f, 0.f);
        if (grow < M) {
            if (MODE == 0) {
                v = ld4(A + (size_t)grow * 128 + k);
            } else if (MODE == 1) {
                v = (k < 128) ? ld4(A + (size_t)grow * 128 + k)
                              : ld4(A2 + (size_t)grow * 128 + (k - 128));
            } else {
                int node = (k < 128) ? __ldg(g1 + grow) : __ldg(g2 + grow);
                int kk = (k < 128) ? k : (k - 128);
                v = ld4(A + (size_t)node * 128 + kk);
            }
        }
        return v;
    };
    auto loadB = [&](int k0) -> float4 {
        int gk = k0 + bk;
        if (MODE == 1)
            return (gk < 128) ? ld4(B + (size_t)gk * 128 + bnc)
                              : ld4(B2 + (size_t)(gk - 128) * 128 + bnc);
        return ld4(B + (size_t)gk * 128 + bnc);
    };
    auto storeTile = [&](int st, float4 va, float4 vb) {
        uint32_t* AsH = S + st * STG_SZ;
        uint32_t* AsL = AsH + A_SZ;
        uint32_t* BsH = AsL + A_SZ;
        uint32_t* BsL = BsH + B_SZ;
        uint4 th, tl;
        tfsplit(va.x, th.x, tl.x); tfsplit(va.y, th.y, tl.y);
        tfsplit(va.z, th.z, tl.z); tfsplit(va.w, th.w, tl.w);
        *(uint4*)&AsH[am * AST + akc] = th;
        *(uint4*)&AsL[am * AST + akc] = tl;
        tfsplit(vb.x, th.x, tl.x); tfsplit(vb.y, th.y, tl.y);
        tfsplit(vb.z, th.z, tl.z); tfsplit(vb.w, th.w, tl.w);
        *(uint4*)&BsH[bk * BST + bnc] = th;
        *(uint4*)&BsL[bk * BST + bnc] = tl;
    };

    // prologue
    {
        float4 va = loadA(0), vb = loadB(0);
        storeTile(0, va, vb);
    }
    __syncthreads();

#pragma unroll 1
    for (int t = 0; t < NT; t++) {
        float4 na, nb;
        if (t + 1 < NT) { na = loadA((t + 1) * 8); nb = loadB((t + 1) * 8); }

        // ---- compute from stage t&1 ----
        {
            const uint32_t* AsH = S + (t & 1) * STG_SZ;
            const uint32_t* AsL = AsH + A_SZ;
            const uint32_t* BsH = AsL + A_SZ;
            const uint32_t* BsL = BsH + B_SZ;
            uint32_t ah[4][4], al[4][4];
#pragma unroll
            for (int mt = 0; mt < 4; mt++) {
                int r = wm * 64 + mt * 16 + grp;
                int o0 = r * AST + qid;
                int o1 = (r + 8) * AST + qid;
                ah[mt][0] = AsH[o0];     ah[mt][1] = AsH[o1];
                ah[mt][2] = AsH[o0 + 4]; ah[mt][3] = AsH[o1 + 4];
                al[mt][0] = AsL[o0];     al[mt][1] = AsL[o1];
                al[mt][2] = AsL[o0 + 4]; al[mt][3] = AsL[o1 + 4];
            }
#pragma unroll
            for (int nt = 0; nt < 4; nt++) {
                int c = wn * 32 + nt * 8 + grp;
                uint32_t bh[2], bl_[2];
                bh[0]  = BsH[qid * BST + c];
                bh[1]  = BsH[(qid + 4) * BST + c];
                bl_[0] = BsL[qid * BST + c];
                bl_[1] = BsL[(qid + 4) * BST + c];
#pragma unroll
                for (int mt = 0; mt < 4; mt++) {
                    mma_tf32(acc[mt][nt], ah[mt], bh);
                    mma_tf32(acc[mt][nt], al[mt], bh);
                    mma_tf32(acc[mt][nt], ah[mt], bl_);
                }
            }
        }

        if (t + 1 < NT) storeTile((t + 1) & 1, na, nb);
        __syncthreads();
    }

    // ---- epilogue ----
    float bv[4][2];
#pragma unroll
    for (int nt = 0; nt < 4; nt++) {
        int c = wn * 32 + nt * 8 + 2 * qid;
        bv[nt][0] = __ldg(bias + c);
        bv[nt][1] = __ldg(bias + c + 1);
    }

    if (MODE == 0) {
#pragma unroll
        for (int mt = 0; mt < 4; mt++) {
#pragma unroll
            for (int half = 0; half < 2; half++) {
                int row = brow + wm * 64 + mt * 16 + grp + half * 8;
                if (row < M) {
#pragma unroll
                    for (int nt = 0; nt < 4; nt++) {
                        int col = wn * 32 + nt * 8 + 2 * qid;
                        float2 o;
                        o.x = fmaxf(acc[mt][nt][half * 2 + 0] + bv[nt][0], 0.f);
                        o.y = fmaxf(acc[mt][nt][half * 2 + 1] + bv[nt][1], 0.f);
                        *(float2*)(C + (size_t)row * 128 + col) = o;
                    }
                }
            }
        }
    } else if (MODE == 1) {
        // fused LayerNorm: per-row sum / sumsq partials -> smem reduce -> normalize
#pragma unroll
        for (int mt = 0; mt < 4; mt++) {
#pragma unroll
            for (int half = 0; half < 2; half++) {
                float s1 = 0.f, s2 = 0.f;
#pragma unroll
                for (int nt = 0; nt < 4; nt++) {
                    float vx = acc[mt][nt][half * 2 + 0] + bv[nt][0];
                    float vy = acc[mt][nt][half * 2 + 1] + bv[nt][1];
                    s1 += vx + vy;
                    s2 += vx * vx + vy * vy;
                }
                s1 += __shfl_down_sync(0xffffffffu, s1, 2);
                s1 += __shfl_down_sync(0xffffffffu, s1, 1);
                s2 += __shfl_down_sync(0xffffffffu, s2, 2);
                s2 += __shfl_down_sync(0xffffffffu, s2, 1);
                if (qid == 0) {
                    int rloc = wm * 64 + mt * 16 + grp + half * 8;
                    s_r1[wn * 128 + rloc] = s1;
                    s_r2[wn * 128 + rloc] = s2;
                }
            }
        }
        __syncthreads();
        if (tid < 128) {
            float sum = s_r1[tid] + s_r1[128 + tid] + s_r1[256 + tid] + s_r1[384 + tid];
            float sq  = s_r2[tid] + s_r2[128 + tid] + s_r2[256 + tid] + s_r2[384 + tid];
            float mu = sum * (1.0f / 128.0f);
            float var = fmaxf(sq * (1.0f / 128.0f) - mu * mu, 0.0f);
            s_mu[tid] = mu;
            s_rs[tid] = rsqrtf(var + 1e-5f);
        }
        __syncthreads();
#pragma unroll
        for (int mt = 0; mt < 4; mt++) {
#pragma unroll
            for (int half = 0; half < 2; half++) {
                int rloc = wm * 64 + mt * 16 + grp + half * 8;
                int row = brow + rloc;
                if (row < M) {
                    float mu = s_mu[rloc], rs = s_rs[rloc];
#pragma unroll
                    for (int nt = 0; nt < 4; nt++) {
                        int col = wn * 32 + nt * 8 + 2 * qid;
                        float vx = acc[mt][nt][half * 2 + 0] + bv[nt][0];
                        float vy = acc[mt][nt][half * 2 + 1] + bv[nt][1];
                        float2 o;
                        o.x = (vx - mu) * rs * __ldg(lnw + col) + __ldg(lnb + col);
                        o.y = (vy - mu) * rs * __ldg(lnw + col + 1) + __ldg(lnb + col + 1);
                        *(float2*)(C + (size_t)row * 128 + col) = o;
                    }
                }
            }
        }
    } else {
        // fused edge-MLP logits
        float w2v[4][2];
#pragma unroll
        for (int nt = 0; nt < 4; nt++) {
            int c = wn * 32 + nt * 8 + 2 * qid;
            w2v[nt][0] = __ldg(W2 + c);
            w2v[nt][1] = __ldg(W2 + c + 1);
        }
#pragma unroll
        for (int mt = 0; mt < 4; mt++) {
#pragma unroll
            for (int half = 0; half < 2; half++) {
                float part = 0.0f;
#pragma unroll
                for (int nt = 0; nt < 4; nt++) {
                    part += fmaxf(acc[mt][nt][half * 2 + 0] + bv[nt][0], 0.f) * w2v[nt][0];
                    part += fmaxf(acc[mt][nt][half * 2 + 1] + bv[nt][1], 0.f) * w2v[nt][1];
                }
                part += __shfl_down_sync(0xffffffffu, part, 2);
                part += __shfl_down_sync(0xffffffffu, part, 1);
                if (qid == 0) {
                    int rloc = wm * 64 + mt * 16 + grp + half * 8;
                    atomicAdd(&red[rloc], part);
                }
            }
        }
        __syncthreads();
        if (tid < 128) {
            int row = brow + tid;
            if (row < M) C[row] = red[tid] + __ldg(b2);
        }
    }
}

// ---------------- launch ----------------
extern "C" void kernel_launch(void* const* d_in, const int* in_sizes, int n_in,
                              void* d_out, int out_size) {
    const float* x     = (const float*)d_in[0];
    const int*   ei    = (const int*)d_in[1];
    const int*   eli   = (const int*)d_in[2];
    const float* p0_Wp = (const float*)d_in[3];
    const float* p0_bp = (const float*)d_in[4];
    const float* p0_Wl = (const float*)d_in[5];
    const float* p0_bl = (const float*)d_in[6];
    const float* p0_Wr = (const float*)d_in[7];
    const float* Wp_s  = (const float*)d_in[8];
    const float* bp_s  = (const float*)d_in[9];
    const float* Wl_s  = (const float*)d_in[10];
    const float* bl_s  = (const float*)d_in[11];
    const float* Wr_s  = (const float*)d_in[12];
    const float* ln_w  = (const float*)d_in[13];
    const float* ln_b  = (const float*)d_in[14];
    const float* e_W1  = (const float*)d_in[15];
    const float* e_b1  = (const float*)d_in[16];
    const float* e_W2  = (const float*)d_in[17];
    const float* e_b2  = (const float*)d_in[18];
    float* out = (float*)d_out;

    const int Nn = in_sizes[0] / 2;
    const int E  = in_sizes[1] / 2;
    const int Q  = in_sizes[2] / 2;

    float *p_h, *p_xp, *p_m, *p_xp0, *p_inv;
    int *p_icnt, *p_rowptr, *p_woff, *p_csrc;
    cudaGetSymbolAddress((void**)&p_h,      g_h);
    cudaGetSymbolAddress((void**)&p_xp,     g_xp);
    cudaGetSymbolAddress((void**)&p_m,      g_m);
    cudaGetSymbolAddress((void**)&p_xp0,    g_xp0);
    cudaGetSymbolAddress((void**)&p_inv,    g_inv);
    cudaGetSymbolAddress((void**)&p_icnt,   g_icnt);
    cudaGetSymbolAddress((void**)&p_rowptr, g_rowptr);
    cudaGetSymbolAddress((void**)&p_woff,   g_woff);
    cudaGetSymbolAddress((void**)&p_csrc,   g_csrc);

    const int* src = ei;
    const int* dst = ei + E;

    // 1: layer-0 projection (also zeroes icnt; no memset launch)
    l0xp_k<<<cdiv(Nn, 256), 256>>>(x, p0_Wp, p0_bp, p_xp0, p_icnt, Nn);
    // 2-4: CSR build (reused by all 3 layers)
    count_k<<<cdiv(E, 256), 256>>>(dst, p_icnt, E);
    scan_k<<<1, 1024>>>(p_icnt, p_rowptr, p_woff, p_inv, Nn);
    scatter_k<<<cdiv(E, 256), 256>>>(src, dst, p_woff, p_csrc, E);
    // 5: layer-0 aggregate+combine+LN
    combine0_ln_k<<<cdiv(Nn, 8), 256>>>(p_rowptr, p_csrc, p_inv, p_xp0,
                                        p0_Wl, p0_bl, p0_Wr, ln_w, ln_b, p_h, Nn);

    // ---- layers 1..2 (H -> H); 6th launch = first GEMM (ncu target) ----
    for (int i = 0; i < 2; i++) {
        mma_gemm_k<0><<<cdiv(Nn, 128), 256>>>(p_h, nullptr, nullptr, nullptr,
                                              Wp_s + (size_t)i * HDIM * HDIM, nullptr,
                                              bp_s + (size_t)i * HDIM, nullptr, nullptr,
                                              nullptr, nullptr, p_xp, Nn);
        agg_csr_k<<<cdiv(Nn, 8), 256>>>(p_xp, p_rowptr, p_csrc, p_inv, p_m, Nn);
        mma_gemm_k<1><<<cdiv(Nn, 128), 256>>>(p_m, p_xp, nullptr, nullptr,
                                              Wl_s + (size_t)i * HDIM * HDIM,
                                              Wr_s + (size_t)i * HDIM * HDIM,
                                              bl_s + (size_t)i * HDIM, nullptr, nullptr,
                                              ln_w + (size_t)(i + 1) * HDIM,
                                              ln_b + (size_t)(i + 1) * HDIM, p_h, Nn);
    }

    // ---- edge MLP (fused logits) ----
    mma_gemm_k<2><<<cdiv(Q, 128), 256>>>(p_h, nullptr, eli, eli + Q,
                                         e_W1, nullptr, e_b1, e_W2, e_b2,
                                         nullptr, nullptr, out, Q);
}